// round 11
// baseline (speedup 1.0000x reference)
#include <cuda_runtime.h>
#include <math.h>

typedef unsigned long long ull;

#define NB   8192
#define NI   1000
#define ND   1000
#define NE   64
#define NATT 16

// ---- scratch (device globals) ----
__device__ __align__(16) float g_e_c [NB * NE];     // [8192,64]
__device__ __align__(16) float g_ac  [NB * NATT];   // [8192,16]
__device__ __align__(16) float g_e_r [NI * NE];     // [1000,64]
__device__ __align__(16) float g_arT [NATT * NI];   // [16,1000] transposed (incl +ba1)

// ---- packed f32x2 helpers ----
__device__ __forceinline__ ull pack2(float lo, float hi) {
    ull r; asm("mov.b64 %0, {%1, %2};" : "=l"(r) : "f"(lo), "f"(hi)); return r;
}
__device__ __forceinline__ void ffma2(ull& d, ull a, ull b) {
    asm("fma.rn.f32x2 %0, %1, %2, %0;" : "+l"(d) : "l"(a), "l"(b));
}
__device__ __forceinline__ ull add2(ull a, ull b) {
    ull r; asm("add.rn.f32x2 %0, %1, %2;" : "=l"(r) : "l"(a), "l"(b)); return r;
}
__device__ __forceinline__ float2 unpack2(ull v) {
    float2 f; asm("mov.b64 {%0, %1}, %2;" : "=f"(f.x), "=f"(f.y) : "l"(v)); return f;
}
__device__ __forceinline__ ull relu_add2(ull a, ull b) {
    float2 f = unpack2(add2(a, b));
    return pack2(fmaxf(f.x, 0.f), fmaxf(f.y, 0.f));
}
// dual exp2 via one MUFU op on fp16x2
__device__ __forceinline__ void exp2_pair(float x0, float x1, float& e0, float& e1) {
    unsigned h2;
    asm("cvt.rn.f16x2.f32 %0, %1, %2;" : "=r"(h2) : "f"(x1), "f"(x0));
    asm("ex2.approx.f16x2 %0, %0;" : "+r"(h2));
    asm("{\n\t.reg .b16 l, h;\n\t"
        "mov.b32 {l, h}, %2;\n\t"
        "cvt.f32.f16 %0, l;\n\t"
        "cvt.f32.f16 %1, h;\n\t}" : "=f"(e0), "=f"(e1) : "r"(h2));
}
__device__ __forceinline__ unsigned smem_u32(const void* p) {
    unsigned a;
    asm("{ .reg .u64 t; cvta.to.shared.u64 t, %1; cvt.u32.u64 %0, t; }" : "=r"(a) : "l"(p));
    return a;
}
#define CP_ASYNC16(s, g) asm volatile("cp.async.cg.shared.global [%0], [%1], 16;" :: "r"(s), "l"(g))
#define CP_COMMIT()      asm volatile("cp.async.commit_group;")
#define CP_WAIT(n)       asm volatile("cp.async.wait_group %0;" :: "n"(n))

// ============================================================================
// k_embed: unified embedding GEMM, cp.async double-buffered, 512 threads.
// (unchanged — best so far)
// ============================================================================
#define KT    40
#define NTILE 25
#define BUFSZ 5632   // (64+64)*44 floats

__global__ __launch_bounds__(512, 1) void k_embed(
        const float* __restrict__ cand, const float* __restrict__ rated,
        const float* __restrict__ We,   const float* __restrict__ be,
        const float* __restrict__ Wa1,  const float* __restrict__ ba1) {
    extern __shared__ __align__(16) float sm[];   // 2*BUFSZ = 11264 floats

    const int t = threadIdx.x;
    const int b = blockIdx.x;
    const bool isC = (b < 128);
    const int row0   = isC ? b * 64 : (b - 128) * 64;
    const int maxrow = isC ? NB : NI;
    const float* __restrict__ A = isC ? cand : rated;

    const int th = t & 255;
    const int kh = t >> 8;
    const int rq = th >> 4;
    const int nq = th & 15;
    const int kc0 = 20 * kh;

    auto load_tile = [&](int kt, int buf) {
        const int k0 = kt * KT;
        float* base = sm + buf * BUFSZ;
        #pragma unroll
        for (int l = 0; l < 3; ++l) {
            int idx = t + 512 * l;
            if (idx < 640) {
                int r = idx / 10, c = idx - r * 10;
                int gr = row0 + r; if (gr >= maxrow) gr = maxrow - 1;
                CP_ASYNC16(smem_u32(base + r * 44 + 4 * c),
                           A + (size_t)gr * ND + k0 + 4 * c);
            } else if (idx < 1280) {
                int idx2 = idx - 640;
                int r = idx2 / 10, c = idx2 - r * 10;
                CP_ASYNC16(smem_u32(base + 2816 + r * 44 + 4 * c),
                           We + (size_t)r * ND + k0 + 4 * c);
            }
        }
    };

    ull acc[4][4];
    #pragma unroll
    for (int r = 0; r < 4; ++r)
        #pragma unroll
        for (int j = 0; j < 4; ++j) acc[r][j] = 0ull;

    load_tile(0, 0);
    CP_COMMIT();

    for (int kt = 0; kt < NTILE; ++kt) {
        const int cur = kt & 1;
        if (kt < NTILE - 1) {
            load_tile(kt + 1, cur ^ 1);
            CP_COMMIT();
            CP_WAIT(1);
        } else {
            CP_WAIT(0);
        }
        __syncthreads();
        const float* a_sm = sm + cur * BUFSZ + kc0;
        const float* b_sm = sm + cur * BUFSZ + 2816 + kc0;
        #pragma unroll
        for (int c = 0; c < 5; ++c) {
            ull alo[4], ahi[4];
            #pragma unroll
            for (int r = 0; r < 4; ++r) {
                float4 av = *(const float4*)(a_sm + (4 * rq + r) * 44 + 4 * c);
                alo[r] = pack2(av.x, av.y);
                ahi[r] = pack2(av.z, av.w);
            }
            #pragma unroll
            for (int j = 0; j < 4; ++j) {
                float4 bv = *(const float4*)(b_sm + (nq + 16 * j) * 44 + 4 * c);
                ull blo = pack2(bv.x, bv.y), bhi = pack2(bv.z, bv.w);
                #pragma unroll
                for (int r = 0; r < 4; ++r) {
                    ffma2(acc[r][j], alo[r], blo);
                    ffma2(acc[r][j], ahi[r], bhi);
                }
            }
        }
        __syncthreads();
    }

    float* ec = sm;              // [64][66]
    float* w1 = sm + 4224;       // [16][66]
    float* ps = sm + 5280;       // [64][65]

    if (kh) {
        #pragma unroll
        for (int r = 0; r < 4; ++r)
            #pragma unroll
            for (int j = 0; j < 4; ++j) {
                float2 f = unpack2(acc[r][j]);
                ps[(4 * rq + r) * 65 + nq + 16 * j] = f.x + f.y;
            }
    }
    for (int idx = t; idx < 1024; idx += 512) {
        int a = idx >> 6, e = idx & 63;
        w1[a * 66 + e] = Wa1[a * 128 + (isC ? 0 : 64) + e];
    }
    __syncthreads();

    float* eout = isC ? g_e_c : g_e_r;
    if (!kh) {
        #pragma unroll
        for (int r = 0; r < 4; ++r) {
            int row = row0 + 4 * rq + r;
            #pragma unroll
            for (int j = 0; j < 4; ++j) {
                float2 f = unpack2(acc[r][j]);
                int n = nq + 16 * j;
                float v = f.x + f.y + ps[(4 * rq + r) * 65 + n] + __ldg(be + n);
                ec[(4 * rq + r) * 66 + n] = v;
                if (row < maxrow) eout[(size_t)row * NE + n] = v;
            }
        }
    }
    __syncthreads();

    for (int o = t; o < 1024; o += 512) {
        int r = o >> 4, a = o & 15;
        ull s = 0ull;
        #pragma unroll
        for (int e2 = 0; e2 < 32; ++e2)
            ffma2(s, *(const ull*)(ec + r * 66 + 2 * e2),
                     *(const ull*)(w1 + a * 66 + 2 * e2));
        float2 f = unpack2(s);
        int row = row0 + r;
        if (row < maxrow) {
            if (isC) g_ac[(size_t)row * NATT + a] = f.x + f.y;
            else     g_arT[a * NI + row] = f.x + f.y + __ldg(ba1 + a);
        }
    }
}

// ============================================================================
// k_attn_mlp: fused scores->exp->x um -> user_emb -> 3-layer MLP -> out.
// 16 b-rows/block, grid 512, 72064 B smem (3 blocks/SM).
// NOTE: part spans [128][64] = 8192 floats (cs[0..8192)). Phase 3 is split
// 3a (reduce part into REGISTERS) / sync / 3b (write xs + stage weights) so
// the xs/Wm1s overlays (4224.., 6400..) never race live partials.
// ============================================================================
__global__ __launch_bounds__(256) void k_attn_mlp(
        const float* __restrict__ um,  const float* __restrict__ Wa2,
        const float* __restrict__ Wm1, const float* __restrict__ bm1,
        const float* __restrict__ Wm2, const float* __restrict__ bm2,
        const float* __restrict__ Wm3, const float* __restrict__ bm3,
        float* __restrict__ out) {
    extern __shared__ __align__(16) float cs[];
    float* sw   = cs;            // [1000][18]  e*um  (18000)
    float* invZ = cs + 18000;    // [16]
    // overlays (sequenced by barriers):
    float* part = cs;            // [128][64] = 8192 phase-2 partials
    float* xs   = cs + 4224;     // [16][134] = 2144  (written AFTER part dead)
    float* Wm1s = cs + 6400;     // [64][130] = 8320  (written AFTER part dead)
    float* Wm2s = cs + 14720;    // [32][66]  = 2112
    float* Wm3s = cs + 16832;    // 32
    float* b1s  = cs + 16864;    // 64
    float* b2s  = cs + 16928;    // 32
    float* b3s  = cs + 16960;    // 4
    float* h1s  = cs;            // [16][66] = 1056 (after part+3a consumed)
    float* h2s  = cs + 1056;     // [16][34] = 544

    const int t  = threadIdx.x;
    const int b0 = blockIdx.x * 16;

    // ---- phase 1: score -> exp2 -> *um, fused ----
    {
        const int bt = t >> 4, g = t & 15;
        const float L2E = 1.4426950408889634f;
        ull w2[16], c2[16];
        {
            const float4* wp = (const float4*)Wa2;
            const float4* ap = (const float4*)(g_ac + (size_t)(b0 + bt) * NATT);
            #pragma unroll
            for (int q = 0; q < 4; ++q) {
                float4 w = wp[q], c = ap[q];
                float wx = w.x * L2E, wy = w.y * L2E, wz = w.z * L2E, ww = w.w * L2E;
                w2[4*q+0] = pack2(wx, wx); c2[4*q+0] = pack2(c.x, c.x);
                w2[4*q+1] = pack2(wy, wy); c2[4*q+1] = pack2(c.y, c.y);
                w2[4*q+2] = pack2(wz, wz); c2[4*q+2] = pack2(c.z, c.z);
                w2[4*q+3] = pack2(ww, ww); c2[4*q+3] = pack2(c.w, c.w);
            }
        }
        float zacc = 0.f;
        const float* __restrict__ umr = um + (size_t)(b0 + bt) * NI;
        for (int i4 = g; i4 < 250; i4 += 16) {
            ull s01 = 0ull, s23 = 0ull;
            #pragma unroll
            for (int a = 0; a < 16; ++a) {
                float4 r4 = *(const float4*)(g_arT + a * NI + 4 * i4);
                ull r01 = pack2(r4.x, r4.y), r23 = pack2(r4.z, r4.w);
                ffma2(s01, w2[a], relu_add2(r01, c2[a]));
                ffma2(s23, w2[a], relu_add2(r23, c2[a]));
            }
            float2 f01 = unpack2(s01), f23 = unpack2(s23);
            float e0, e1, e2, e3;
            exp2_pair(fminf(f01.x, 14.f), fminf(f01.y, 14.f), e0, e1);
            exp2_pair(fminf(f23.x, 14.f), fminf(f23.y, 14.f), e2, e3);
            zacc += (e0 + e1) + (e2 + e3);
            float4 u = *(const float4*)(umr + 4 * i4);
            const int i = 4 * i4;
            sw[(i    ) * 18 + bt] = e0 * u.x;
            sw[(i + 1) * 18 + bt] = e1 * u.y;
            sw[(i + 2) * 18 + bt] = e2 * u.z;
            sw[(i + 3) * 18 + bt] = e3 * u.w;
        }
        #pragma unroll
        for (int o = 8; o; o >>= 1)
            zacc += __shfl_down_sync(0xffffffffu, zacc, o, 16);
        if (g == 0) invZ[bt] = 1.f / zacc;
    }
    __syncthreads();

    // ---- phase 2: user_emb partial GEMM; 2 d/thread, bt-paired f32x2 ----
    {
        const int dp = t & 31;       // d = 2dp, 2dp+1
        const int g3 = t >> 5;       // 0..7
        ull acc[8][2];
        #pragma unroll
        for (int j = 0; j < 8; ++j) { acc[j][0] = 0ull; acc[j][1] = 0ull; }
        for (int i = g3; i < NI; i += 8) {
            float2 ev = *(const float2*)(g_e_r + (size_t)i * NE + 2 * dp);
            ull ex = pack2(ev.x, ev.x), ey = pack2(ev.y, ev.y);
            const ull* wp = (const ull*)(sw + i * 18);
            #pragma unroll
            for (int j = 0; j < 8; ++j) {
                ull wv = wp[j];
                ffma2(acc[j][0], ex, wv);
                ffma2(acc[j][1], ey, wv);
            }
        }
        __syncthreads();   // all sw reads done before partial overlay
        #pragma unroll
        for (int j = 0; j < 8; ++j) {
            float2 f0 = unpack2(acc[j][0]);
            float2 f1 = unpack2(acc[j][1]);
            *(float2*)(part + (g3 * 16 + 2 * j    ) * 64 + 2 * dp) = make_float2(f0.x, f1.x);
            *(float2*)(part + (g3 * 16 + 2 * j + 1) * 64 + 2 * dp) = make_float2(f0.y, f1.y);
        }
    }
    __syncthreads();

    // ---- phase 3a: reduce partials into REGISTERS (part region live) ----
    float uv[4], ev4[4];
    {
        #pragma unroll
        for (int l = 0; l < 4; ++l) {
            int idx = t + 256 * l;
            int bt = idx >> 6, dd = idx & 63;
            float v = 0.f;
            #pragma unroll
            for (int p = 0; p < 8; ++p) v += part[(p * 16 + bt) * 64 + dd];
            uv[l]  = v * invZ[bt];
            ev4[l] = g_e_c[(size_t)(b0 + bt) * NE + dd];
        }
    }
    __syncthreads();   // part is DEAD from here; xs/Wm1s overlays now safe

    // ---- phase 3b: write xs, stage MLP weights ----
    #pragma unroll
    for (int l = 0; l < 4; ++l) {
        int idx = t + 256 * l;
        int bt = idx >> 6, dd = idx & 63;
        xs[bt * 134 + 64 + dd] = uv[l];
        xs[bt * 134 + dd]      = ev4[l];
    }
    for (int idx = t; idx < 8192; idx += 256) {
        int n = idx >> 7, k = idx & 127;
        Wm1s[n * 130 + k] = Wm1[idx];
    }
    for (int idx = t; idx < 2048; idx += 256) {
        int n = idx >> 6, k = idx & 63;
        Wm2s[n * 66 + k] = Wm2[idx];
    }
    if (t < 32) Wm3s[t] = Wm3[t];
    if (t < 64) b1s[t]  = bm1[t];
    if (t < 32) b2s[t]  = bm2[t];
    if (t == 0) b3s[0]  = bm3[0];
    __syncthreads();

    // ---- MLP L1: [16,128]@[128,64] ; thread = (row = t&15, nq = t>>4), 4 n each
    {
        const int row = t & 15, nq = t >> 4;
        ull acc[4];
        #pragma unroll
        for (int j = 0; j < 4; ++j) acc[j] = 0ull;
        #pragma unroll 8
        for (int kk = 0; kk < 64; ++kk) {
            ull a = *(const ull*)(xs + row * 134 + 2 * kk);
            #pragma unroll
            for (int j = 0; j < 4; ++j)
                ffma2(acc[j], a, *(const ull*)(Wm1s + (nq + 16 * j) * 130 + 2 * kk));
        }
        float hv[4];
        #pragma unroll
        for (int j = 0; j < 4; ++j) {
            float2 f = unpack2(acc[j]);
            hv[j] = fmaxf(f.x + f.y + b1s[nq + 16 * j], 0.f);
        }
        __syncthreads();   // all xs/weight reads done before h1s overlay of cs[0..]
        #pragma unroll
        for (int j = 0; j < 4; ++j)
            h1s[row * 66 + nq + 16 * j] = hv[j];
    }
    __syncthreads();

    // ---- MLP L2: [16,64]@[64,32] ; thread = (row = t&15, nq = t>>4), 2 n each
    {
        const int row = t & 15, nq = t >> 4;
        ull acc0 = 0ull, acc1 = 0ull;
        #pragma unroll 8
        for (int kk = 0; kk < 32; ++kk) {
            ull h = *(const ull*)(h1s + row * 66 + 2 * kk);
            ffma2(acc0, h, *(const ull*)(Wm2s + nq * 66 + 2 * kk));
            ffma2(acc1, h, *(const ull*)(Wm2s + (nq + 16) * 66 + 2 * kk));
        }
        float2 f0 = unpack2(acc0), f1 = unpack2(acc1);
        h2s[row * 34 + nq]      = fmaxf(f0.x + f0.y + b2s[nq], 0.f);
        h2s[row * 34 + nq + 16] = fmaxf(f1.x + f1.y + b2s[nq + 16], 0.f);
    }
    __syncthreads();

    // ---- MLP L3: dot-32 per row ----
    if (t < 16) {
        ull acc = 0ull;
        #pragma unroll
        for (int kk = 0; kk < 16; ++kk)
            ffma2(acc, *(const ull*)(h2s + t * 34 + 2 * kk),
                       *(const ull*)(Wm3s + 2 * kk));
        float2 f = unpack2(acc);
        out[b0 + t] = f.x + f.y + b3s[0];
    }
}

// ============================================================================
extern "C" void kernel_launch(void* const* d_in, const int* in_sizes, int n_in,
                              void* d_out, int out_size) {
    const float* cand  = (const float*)d_in[0];
    const float* rated = (const float*)d_in[1];
    const float* um    = (const float*)d_in[2];
    const float* We    = (const float*)d_in[3];
    const float* be    = (const float*)d_in[4];
    const float* Wa1   = (const float*)d_in[5];
    const float* ba1   = (const float*)d_in[6];
    const float* Wa2   = (const float*)d_in[7];
    // d_in[8] = ba2: cancels in softmax
    const float* Wm1   = (const float*)d_in[9];
    const float* bm1   = (const float*)d_in[10];
    const float* Wm2   = (const float*)d_in[11];
    const float* bm2   = (const float*)d_in[12];
    const float* Wm3   = (const float*)d_in[13];
    const float* bm3   = (const float*)d_in[14];
    float* out = (float*)d_out;

    const int ESM = 11264 * 4;   // 45056 B
    const int CSM = 18016 * 4;   // 72064 B
    cudaFuncSetAttribute(k_embed,    cudaFuncAttributeMaxDynamicSharedMemorySize, ESM);
    cudaFuncSetAttribute(k_attn_mlp, cudaFuncAttributeMaxDynamicSharedMemorySize, CSM);

    k_embed   <<<144, 512, ESM>>>(cand, rated, We, be, Wa1, ba1);
    k_attn_mlp<<<512, 256, CSM>>>(um, Wa2, Wm1, bm1, Wm2, bm2, Wm3, bm3, out);
}

// round 13
// speedup vs baseline: 1.1774x; 1.1774x over previous
#include <cuda_runtime.h>
#include <math.h>

typedef unsigned long long ull;

#define NB   8192
#define NI   1000
#define ND   1000
#define NE   64
#define NATT 16

// ---- scratch (device globals) ----
__device__ __align__(16) float g_e_c [NB * NE];     // [8192,64]
__device__ __align__(16) float g_ac  [NB * NATT];   // [8192,16]
__device__ __align__(16) float g_e_r [NI * NE];     // [1000,64]
__device__ __align__(16) float g_arT [NATT * NI];   // [16,1000] transposed (incl +ba1)

// ---- packed f32x2 helpers ----
__device__ __forceinline__ ull pack2(float lo, float hi) {
    ull r; asm("mov.b64 %0, {%1, %2};" : "=l"(r) : "f"(lo), "f"(hi)); return r;
}
__device__ __forceinline__ void ffma2(ull& d, ull a, ull b) {
    asm("fma.rn.f32x2 %0, %1, %2, %0;" : "+l"(d) : "l"(a), "l"(b));
}
__device__ __forceinline__ ull add2(ull a, ull b) {
    ull r; asm("add.rn.f32x2 %0, %1, %2;" : "=l"(r) : "l"(a), "l"(b)); return r;
}
__device__ __forceinline__ float2 unpack2(ull v) {
    float2 f; asm("mov.b64 {%0, %1}, %2;" : "=f"(f.x), "=f"(f.y) : "l"(v)); return f;
}
__device__ __forceinline__ ull relu_add2(ull a, ull b) {
    float2 f = unpack2(add2(a, b));
    return pack2(fmaxf(f.x, 0.f), fmaxf(f.y, 0.f));
}
// dual exp2 via one MUFU op on fp16x2
__device__ __forceinline__ void exp2_pair(float x0, float x1, float& e0, float& e1) {
    unsigned h2;
    asm("cvt.rn.f16x2.f32 %0, %1, %2;" : "=r"(h2) : "f"(x1), "f"(x0));
    asm("ex2.approx.f16x2 %0, %0;" : "+r"(h2));
    asm("{\n\t.reg .b16 l, h;\n\t"
        "mov.b32 {l, h}, %2;\n\t"
        "cvt.f32.f16 %0, l;\n\t"
        "cvt.f32.f16 %1, h;\n\t}" : "=f"(e0), "=f"(e1) : "r"(h2));
}
__device__ __forceinline__ unsigned smem_u32(const void* p) {
    unsigned a;
    asm("{ .reg .u64 t; cvta.to.shared.u64 t, %1; cvt.u32.u64 %0, t; }" : "=r"(a) : "l"(p));
    return a;
}
#define CP_ASYNC16(s, g) asm volatile("cp.async.cg.shared.global [%0], [%1], 16;" :: "r"(s), "l"(g))
#define CP_COMMIT()      asm volatile("cp.async.commit_group;")
#define CP_WAIT(n)       asm volatile("cp.async.wait_group %0;" :: "n"(n))

// ============================================================================
// k_embed: unified embedding GEMM, cp.async double-buffered, 512 threads.
// (unchanged — passing, 44.8us cold)
// ============================================================================
#define KT    40
#define NTILE 25
#define BUFSZ 5632   // (64+64)*44 floats

__global__ __launch_bounds__(512, 1) void k_embed(
        const float* __restrict__ cand, const float* __restrict__ rated,
        const float* __restrict__ We,   const float* __restrict__ be,
        const float* __restrict__ Wa1,  const float* __restrict__ ba1) {
    extern __shared__ __align__(16) float sm[];   // 2*BUFSZ = 11264 floats

    const int t = threadIdx.x;
    const int b = blockIdx.x;
    const bool isC = (b < 128);
    const int row0   = isC ? b * 64 : (b - 128) * 64;
    const int maxrow = isC ? NB : NI;
    const float* __restrict__ A = isC ? cand : rated;

    const int th = t & 255;
    const int kh = t >> 8;
    const int rq = th >> 4;
    const int nq = th & 15;
    const int kc0 = 20 * kh;

    auto load_tile = [&](int kt, int buf) {
        const int k0 = kt * KT;
        float* base = sm + buf * BUFSZ;
        #pragma unroll
        for (int l = 0; l < 3; ++l) {
            int idx = t + 512 * l;
            if (idx < 640) {
                int r = idx / 10, c = idx - r * 10;
                int gr = row0 + r; if (gr >= maxrow) gr = maxrow - 1;
                CP_ASYNC16(smem_u32(base + r * 44 + 4 * c),
                           A + (size_t)gr * ND + k0 + 4 * c);
            } else if (idx < 1280) {
                int idx2 = idx - 640;
                int r = idx2 / 10, c = idx2 - r * 10;
                CP_ASYNC16(smem_u32(base + 2816 + r * 44 + 4 * c),
                           We + (size_t)r * ND + k0 + 4 * c);
            }
        }
    };

    ull acc[4][4];
    #pragma unroll
    for (int r = 0; r < 4; ++r)
        #pragma unroll
        for (int j = 0; j < 4; ++j) acc[r][j] = 0ull;

    load_tile(0, 0);
    CP_COMMIT();

    for (int kt = 0; kt < NTILE; ++kt) {
        const int cur = kt & 1;
        if (kt < NTILE - 1) {
            load_tile(kt + 1, cur ^ 1);
            CP_COMMIT();
            CP_WAIT(1);
        } else {
            CP_WAIT(0);
        }
        __syncthreads();
        const float* a_sm = sm + cur * BUFSZ + kc0;
        const float* b_sm = sm + cur * BUFSZ + 2816 + kc0;
        #pragma unroll
        for (int c = 0; c < 5; ++c) {
            ull alo[4], ahi[4];
            #pragma unroll
            for (int r = 0; r < 4; ++r) {
                float4 av = *(const float4*)(a_sm + (4 * rq + r) * 44 + 4 * c);
                alo[r] = pack2(av.x, av.y);
                ahi[r] = pack2(av.z, av.w);
            }
            #pragma unroll
            for (int j = 0; j < 4; ++j) {
                float4 bv = *(const float4*)(b_sm + (nq + 16 * j) * 44 + 4 * c);
                ull blo = pack2(bv.x, bv.y), bhi = pack2(bv.z, bv.w);
                #pragma unroll
                for (int r = 0; r < 4; ++r) {
                    ffma2(acc[r][j], alo[r], blo);
                    ffma2(acc[r][j], ahi[r], bhi);
                }
            }
        }
        __syncthreads();
    }

    float* ec = sm;              // [64][66]
    float* w1 = sm + 4224;       // [16][66]
    float* ps = sm + 5280;       // [64][65]

    if (kh) {
        #pragma unroll
        for (int r = 0; r < 4; ++r)
            #pragma unroll
            for (int j = 0; j < 4; ++j) {
                float2 f = unpack2(acc[r][j]);
                ps[(4 * rq + r) * 65 + nq + 16 * j] = f.x + f.y;
            }
    }
    for (int idx = t; idx < 1024; idx += 512) {
        int a = idx >> 6, e = idx & 63;
        w1[a * 66 + e] = Wa1[a * 128 + (isC ? 0 : 64) + e];
    }
    __syncthreads();

    float* eout = isC ? g_e_c : g_e_r;
    if (!kh) {
        #pragma unroll
        for (int r = 0; r < 4; ++r) {
            int row = row0 + 4 * rq + r;
            #pragma unroll
            for (int j = 0; j < 4; ++j) {
                float2 f = unpack2(acc[r][j]);
                int n = nq + 16 * j;
                float v = f.x + f.y + ps[(4 * rq + r) * 65 + n] + __ldg(be + n);
                ec[(4 * rq + r) * 66 + n] = v;
                if (row < maxrow) eout[(size_t)row * NE + n] = v;
            }
        }
    }
    __syncthreads();

    for (int o = t; o < 1024; o += 512) {
        int r = o >> 4, a = o & 15;
        ull s = 0ull;
        #pragma unroll
        for (int e2 = 0; e2 < 32; ++e2)
            ffma2(s, *(const ull*)(ec + r * 66 + 2 * e2),
                     *(const ull*)(w1 + a * 66 + 2 * e2));
        float2 f = unpack2(s);
        int row = row0 + r;
        if (row < maxrow) {
            if (isC) g_ac[(size_t)row * NATT + a] = f.x + f.y;
            else     g_arT[a * NI + row] = f.x + f.y + __ldg(ba1 + a);
        }
    }
}

// ============================================================================
// k_attn_mlp v3: i-CHUNKED (2x500) so smem = 36KB -> 2 blocks/SM, L1D ~156KB.
// g_arT (64KB) becomes L1-resident; MLP weights read straight from global.
// Phase-2 accumulators persist in registers across chunks (numerics identical).
// ============================================================================
__global__ __launch_bounds__(256, 2) void k_attn_mlp(
        const float* __restrict__ um,  const float* __restrict__ Wa2,
        const float* __restrict__ Wm1, const float* __restrict__ bm1,
        const float* __restrict__ Wm2, const float* __restrict__ bm2,
        const float* __restrict__ Wm3, const float* __restrict__ bm3,
        float* __restrict__ out) {
    extern __shared__ __align__(16) float cs[];
    float* sw   = cs;            // [500][18] = 9000 (per chunk)
    float* invZ = cs + 9000;     // [16]
    // overlays (barrier-sequenced):
    float* part = cs;            // [128][64] = 8192 (after all sw reads)
    float* xs   = cs;            // [16][134] = 2144 (after part dead)
    float* h1s  = cs + 2144;     // [16][66]  = 1056
    float* h2s  = cs + 3200;     // [16][34]  = 544

    const int t  = threadIdx.x;
    const int b0 = blockIdx.x * 16;
    const int bt = t >> 4, g = t & 15;     // phase-1 mapping
    const int dp = t & 31, g3 = t >> 5;    // phase-2 mapping

    // phase-2 accumulators persist across chunks
    ull acc[8][2];
    #pragma unroll
    for (int j = 0; j < 8; ++j) { acc[j][0] = 0ull; acc[j][1] = 0ull; }
    float zacc = 0.f;

    // phase-1 constants (L2E folded into Wa2)
    const float L2E = 1.4426950408889634f;
    ull w2[16], c2[16];
    {
        const float4* wp = (const float4*)Wa2;
        const float4* ap = (const float4*)(g_ac + (size_t)(b0 + bt) * NATT);
        #pragma unroll
        for (int q = 0; q < 4; ++q) {
            float4 w = wp[q], c = ap[q];
            float wx = w.x * L2E, wy = w.y * L2E, wz = w.z * L2E, ww = w.w * L2E;
            w2[4*q+0] = pack2(wx, wx); c2[4*q+0] = pack2(c.x, c.x);
            w2[4*q+1] = pack2(wy, wy); c2[4*q+1] = pack2(c.y, c.y);
            w2[4*q+2] = pack2(wz, wz); c2[4*q+2] = pack2(c.z, c.z);
            w2[4*q+3] = pack2(ww, ww); c2[4*q+3] = pack2(c.w, c.w);
        }
    }
    const float* __restrict__ umr = um + (size_t)(b0 + bt) * NI;

    #pragma unroll 1
    for (int c = 0; c < 2; ++c) {
        const int i4lo = 125 * c, i4hi = 125 * (c + 1);
        // ---- phase 1 (chunk c): score -> exp2 -> *um into sw ----
        for (int i4 = i4lo + g; i4 < i4hi; i4 += 16) {
            ull s01 = 0ull, s23 = 0ull;
            #pragma unroll
            for (int a = 0; a < 16; ++a) {
                float4 r4 = *(const float4*)(g_arT + a * NI + 4 * i4);
                ull r01 = pack2(r4.x, r4.y), r23 = pack2(r4.z, r4.w);
                ffma2(s01, w2[a], relu_add2(r01, c2[a]));
                ffma2(s23, w2[a], relu_add2(r23, c2[a]));
            }
            float2 f01 = unpack2(s01), f23 = unpack2(s23);
            float e0, e1, e2, e3;
            exp2_pair(fminf(f01.x, 14.f), fminf(f01.y, 14.f), e0, e1);
            exp2_pair(fminf(f23.x, 14.f), fminf(f23.y, 14.f), e2, e3);
            zacc += (e0 + e1) + (e2 + e3);
            float4 u = *(const float4*)(umr + 4 * i4);
            const int il = 4 * (i4 - i4lo);
            sw[(il    ) * 18 + bt] = e0 * u.x;
            sw[(il + 1) * 18 + bt] = e1 * u.y;
            sw[(il + 2) * 18 + bt] = e2 * u.z;
            sw[(il + 3) * 18 + bt] = e3 * u.w;
        }
        __syncthreads();

        // ---- phase 2 (chunk c): accumulate user_emb partials ----
        const int ilo = 500 * c, ihi = 500 * (c + 1);
        for (int i = ilo + g3; i < ihi; i += 8) {
            float2 ev = *(const float2*)(g_e_r + (size_t)i * NE + 2 * dp);
            ull ex = pack2(ev.x, ev.x), ey = pack2(ev.y, ev.y);
            const ull* wp = (const ull*)(sw + (i - ilo) * 18);
            #pragma unroll
            for (int j = 0; j < 8; ++j) {
                ull wv = wp[j];
                ffma2(acc[j][0], ex, wv);
                ffma2(acc[j][1], ey, wv);
            }
        }
        __syncthreads();   // sw dead (until next chunk rewrites it)
    }

    // ---- Z reduce + invZ; partials to smem ----
    {
        float z = zacc;
        #pragma unroll
        for (int o = 8; o; o >>= 1)
            z += __shfl_down_sync(0xffffffffu, z, o, 16);
        if (g == 0) invZ[bt] = 1.f / z;
    }
    #pragma unroll
    for (int j = 0; j < 8; ++j) {
        float2 f0 = unpack2(acc[j][0]);
        float2 f1 = unpack2(acc[j][1]);
        *(float2*)(part + (g3 * 16 + 2 * j    ) * 64 + 2 * dp) = make_float2(f0.x, f1.x);
        *(float2*)(part + (g3 * 16 + 2 * j + 1) * 64 + 2 * dp) = make_float2(f0.y, f1.y);
    }
    __syncthreads();

    // ---- 3a: reduce partials into registers ----
    float uv[4], ev4[4];
    #pragma unroll
    for (int l = 0; l < 4; ++l) {
        int idx = t + 256 * l;
        int btl = idx >> 6, dd = idx & 63;
        float v = 0.f;
        #pragma unroll
        for (int p = 0; p < 8; ++p) v += part[(p * 16 + btl) * 64 + dd];
        uv[l]  = v * invZ[btl];
        ev4[l] = g_e_c[(size_t)(b0 + btl) * NE + dd];
    }
    __syncthreads();   // part dead

    // ---- 3b: write xs ----
    #pragma unroll
    for (int l = 0; l < 4; ++l) {
        int idx = t + 256 * l;
        int btl = idx >> 6, dd = idx & 63;
        xs[btl * 134 + 64 + dd] = uv[l];
        xs[btl * 134 + dd]      = ev4[l];
    }
    __syncthreads();

    // ---- MLP L1: [16,128]@[128,64]; weights from GLOBAL (L1-hot, uniform) ----
    {
        const int row = t & 15, nq = t >> 4;
        ull a4[4];
        #pragma unroll
        for (int j = 0; j < 4; ++j) a4[j] = 0ull;
        #pragma unroll 8
        for (int kk = 0; kk < 64; ++kk) {
            ull a = *(const ull*)(xs + row * 134 + 2 * kk);
            #pragma unroll
            for (int j = 0; j < 4; ++j)
                ffma2(a4[j], a, *(const ull*)(Wm1 + (size_t)(nq + 16 * j) * 128 + 2 * kk));
        }
        #pragma unroll
        for (int j = 0; j < 4; ++j) {
            float2 f = unpack2(a4[j]);
            int n = nq + 16 * j;
            h1s[row * 66 + n] = fmaxf(f.x + f.y + __ldg(bm1 + n), 0.f);
        }
    }
    __syncthreads();

    // ---- MLP L2: [16,64]@[64,32] ----
    {
        const int row = t & 15, nq = t >> 4;
        ull a0 = 0ull, a1 = 0ull;
        #pragma unroll 8
        for (int kk = 0; kk < 32; ++kk) {
            ull h = *(const ull*)(h1s + row * 66 + 2 * kk);
            ffma2(a0, h, *(const ull*)(Wm2 + (size_t)nq * 64 + 2 * kk));
            ffma2(a1, h, *(const ull*)(Wm2 + (size_t)(nq + 16) * 64 + 2 * kk));
        }
        float2 f0 = unpack2(a0), f1 = unpack2(a1);
        h2s[row * 34 + nq]      = fmaxf(f0.x + f0.y + __ldg(bm2 + nq), 0.f);
        h2s[row * 34 + nq + 16] = fmaxf(f1.x + f1.y + __ldg(bm2 + nq + 16), 0.f);
    }
    __syncthreads();

    // ---- MLP L3: dot-32 per row ----
    if (t < 16) {
        ull a = 0ull;
        #pragma unroll
        for (int kk = 0; kk < 16; ++kk)
            ffma2(a, *(const ull*)(h2s + t * 34 + 2 * kk),
                     *(const ull*)(Wm3 + 2 * kk));
        float2 f = unpack2(a);
        out[b0 + t] = f.x + f.y + __ldg(bm3);
    }
}

// ============================================================================
extern "C" void kernel_launch(void* const* d_in, const int* in_sizes, int n_in,
                              void* d_out, int out_size) {
    const float* cand  = (const float*)d_in[0];
    const float* rated = (const float*)d_in[1];
    const float* um    = (const float*)d_in[2];
    const float* We    = (const float*)d_in[3];
    const float* be    = (const float*)d_in[4];
    const float* Wa1   = (const float*)d_in[5];
    const float* ba1   = (const float*)d_in[6];
    const float* Wa2   = (const float*)d_in[7];
    // d_in[8] = ba2: cancels in softmax
    const float* Wm1   = (const float*)d_in[9];
    const float* bm1   = (const float*)d_in[10];
    const float* Wm2   = (const float*)d_in[11];
    const float* bm2   = (const float*)d_in[12];
    const float* Wm3   = (const float*)d_in[13];
    const float* bm3   = (const float*)d_in[14];
    float* out = (float*)d_out;

    const int ESM = 11264 * 4;   // 45056 B
    const int CSM = 9016 * 4;    // 36064 B
    cudaFuncSetAttribute(k_embed,    cudaFuncAttributeMaxDynamicSharedMemorySize, ESM);
    cudaFuncSetAttribute(k_attn_mlp, cudaFuncAttributeMaxDynamicSharedMemorySize, CSM);

    k_embed   <<<144, 512, ESM>>>(cand, rated, We, be, Wa1, ba1);
    k_attn_mlp<<<512, 256, CSM>>>(um, Wa2, Wm1, bm1, Wm2, bm2, Wm3, bm3, out);
}

// round 15
// speedup vs baseline: 1.2658x; 1.0751x over previous
#include <cuda_runtime.h>
#include <math.h>

typedef unsigned long long ull;

#define NB   8192
#define NI   1000
#define ND   1000
#define NE   64
#define NATT 16

// ---- scratch (device globals) ----
__device__ __align__(16) float g_e_c [NB * NE];     // [8192,64]
__device__ __align__(16) float g_ac  [NB * NATT];   // [8192,16]
__device__ __align__(16) float g_e_r [NI * NE];     // [1000,64]
__device__ __align__(16) float g_arT [NATT * NI];   // [16,1000] transposed (incl +ba1)

// ---- packed f32x2 helpers ----
__device__ __forceinline__ ull pack2(float lo, float hi) {
    ull r; asm("mov.b64 %0, {%1, %2};" : "=l"(r) : "f"(lo), "f"(hi)); return r;
}
__device__ __forceinline__ void ffma2(ull& d, ull a, ull b) {
    asm("fma.rn.f32x2 %0, %1, %2, %0;" : "+l"(d) : "l"(a), "l"(b));
}
__device__ __forceinline__ ull add2(ull a, ull b) {
    ull r; asm("add.rn.f32x2 %0, %1, %2;" : "=l"(r) : "l"(a), "l"(b)); return r;
}
__device__ __forceinline__ float2 unpack2(ull v) {
    float2 f; asm("mov.b64 {%0, %1}, %2;" : "=f"(f.x), "=f"(f.y) : "l"(v)); return f;
}
__device__ __forceinline__ ull relu_add2(ull a, ull b) {
    float2 f = unpack2(add2(a, b));
    return pack2(fmaxf(f.x, 0.f), fmaxf(f.y, 0.f));
}
// dual exp2 via one MUFU op on fp16x2
__device__ __forceinline__ void exp2_pair(float x0, float x1, float& e0, float& e1) {
    unsigned h2;
    asm("cvt.rn.f16x2.f32 %0, %1, %2;" : "=r"(h2) : "f"(x1), "f"(x0));
    asm("ex2.approx.f16x2 %0, %0;" : "+r"(h2));
    asm("{\n\t.reg .b16 l, h;\n\t"
        "mov.b32 {l, h}, %2;\n\t"
        "cvt.f32.f16 %0, l;\n\t"
        "cvt.f32.f16 %1, h;\n\t}" : "=f"(e0), "=f"(e1) : "r"(h2));
}
__device__ __forceinline__ unsigned smem_u32(const void* p) {
    unsigned a;
    asm("{ .reg .u64 t; cvta.to.shared.u64 t, %1; cvt.u32.u64 %0, t; }" : "=r"(a) : "l"(p));
    return a;
}
#define CP_ASYNC16(s, g) asm volatile("cp.async.cg.shared.global [%0], [%1], 16;" :: "r"(s), "l"(g))
#define CP_COMMIT()      asm volatile("cp.async.commit_group;")
#define CP_WAIT(n)       asm volatile("cp.async.wait_group %0;" :: "n"(n))

// ============================================================================
// k_embed: unified embedding GEMM, cp.async double-buffered, 512 threads.
// (unchanged — passing)
// ============================================================================
#define KT    40
#define NTILE 25
#define BUFSZ 5632   // (64+64)*44 floats

__global__ __launch_bounds__(512, 1) void k_embed(
        const float* __restrict__ cand, const float* __restrict__ rated,
        const float* __restrict__ We,   const float* __restrict__ be,
        const float* __restrict__ Wa1,  const float* __restrict__ ba1) {
    extern __shared__ __align__(16) float sm[];   // 2*BUFSZ = 11264 floats

    const int t = threadIdx.x;
    const int b = blockIdx.x;
    const bool isC = (b < 128);
    const int row0   = isC ? b * 64 : (b - 128) * 64;
    const int maxrow = isC ? NB : NI;
    const float* __restrict__ A = isC ? cand : rated;

    const int th = t & 255;
    const int kh = t >> 8;
    const int rq = th >> 4;
    const int nq = th & 15;
    const int kc0 = 20 * kh;

    auto load_tile = [&](int kt, int buf) {
        const int k0 = kt * KT;
        float* base = sm + buf * BUFSZ;
        #pragma unroll
        for (int l = 0; l < 3; ++l) {
            int idx = t + 512 * l;
            if (idx < 640) {
                int r = idx / 10, c = idx - r * 10;
                int gr = row0 + r; if (gr >= maxrow) gr = maxrow - 1;
                CP_ASYNC16(smem_u32(base + r * 44 + 4 * c),
                           A + (size_t)gr * ND + k0 + 4 * c);
            } else if (idx < 1280) {
                int idx2 = idx - 640;
                int r = idx2 / 10, c = idx2 - r * 10;
                CP_ASYNC16(smem_u32(base + 2816 + r * 44 + 4 * c),
                           We + (size_t)r * ND + k0 + 4 * c);
            }
        }
    };

    ull acc[4][4];
    #pragma unroll
    for (int r = 0; r < 4; ++r)
        #pragma unroll
        for (int j = 0; j < 4; ++j) acc[r][j] = 0ull;

    load_tile(0, 0);
    CP_COMMIT();

    for (int kt = 0; kt < NTILE; ++kt) {
        const int cur = kt & 1;
        if (kt < NTILE - 1) {
            load_tile(kt + 1, cur ^ 1);
            CP_COMMIT();
            CP_WAIT(1);
        } else {
            CP_WAIT(0);
        }
        __syncthreads();
        const float* a_sm = sm + cur * BUFSZ + kc0;
        const float* b_sm = sm + cur * BUFSZ + 2816 + kc0;
        #pragma unroll
        for (int c = 0; c < 5; ++c) {
            ull alo[4], ahi[4];
            #pragma unroll
            for (int r = 0; r < 4; ++r) {
                float4 av = *(const float4*)(a_sm + (4 * rq + r) * 44 + 4 * c);
                alo[r] = pack2(av.x, av.y);
                ahi[r] = pack2(av.z, av.w);
            }
            #pragma unroll
            for (int j = 0; j < 4; ++j) {
                float4 bv = *(const float4*)(b_sm + (nq + 16 * j) * 44 + 4 * c);
                ull blo = pack2(bv.x, bv.y), bhi = pack2(bv.z, bv.w);
                #pragma unroll
                for (int r = 0; r < 4; ++r) {
                    ffma2(acc[r][j], alo[r], blo);
                    ffma2(acc[r][j], ahi[r], bhi);
                }
            }
        }
        __syncthreads();
    }

    float* ec = sm;              // [64][66]
    float* w1 = sm + 4224;       // [16][66]
    float* ps = sm + 5280;       // [64][65]

    if (kh) {
        #pragma unroll
        for (int r = 0; r < 4; ++r)
            #pragma unroll
            for (int j = 0; j < 4; ++j) {
                float2 f = unpack2(acc[r][j]);
                ps[(4 * rq + r) * 65 + nq + 16 * j] = f.x + f.y;
            }
    }
    for (int idx = t; idx < 1024; idx += 512) {
        int a = idx >> 6, e = idx & 63;
        w1[a * 66 + e] = Wa1[a * 128 + (isC ? 0 : 64) + e];
    }
    __syncthreads();

    float* eout = isC ? g_e_c : g_e_r;
    if (!kh) {
        #pragma unroll
        for (int r = 0; r < 4; ++r) {
            int row = row0 + 4 * rq + r;
            #pragma unroll
            for (int j = 0; j < 4; ++j) {
                float2 f = unpack2(acc[r][j]);
                int n = nq + 16 * j;
                float v = f.x + f.y + ps[(4 * rq + r) * 65 + n] + __ldg(be + n);
                ec[(4 * rq + r) * 66 + n] = v;
                if (row < maxrow) eout[(size_t)row * NE + n] = v;
            }
        }
    }
    __syncthreads();

    for (int o = t; o < 1024; o += 512) {
        int r = o >> 4, a = o & 15;
        ull s = 0ull;
        #pragma unroll
        for (int e2 = 0; e2 < 32; ++e2)
            ffma2(s, *(const ull*)(ec + r * 66 + 2 * e2),
                     *(const ull*)(w1 + a * 66 + 2 * e2));
        float2 f = unpack2(s);
        int row = row0 + r;
        if (row < maxrow) {
            if (isC) g_ac[(size_t)row * NATT + a] = f.x + f.y;
            else     g_arT[a * NI + row] = f.x + f.y + __ldg(ba1 + a);
        }
    }
}

// ============================================================================
// k_attn_mlp v4: INVERTED phase-1 mapping — each thread owns 2 i x all 16 bt.
// arT loaded ONCE per thread (16 LDG.64/chunk vs ~125 LDG.128 before);
// (ac,Wa2) constants as pre-packed smem ull tables (LDS.64 broadcast).
// 2 chunks of 500 i; smem ~38KB -> 2 blocks/SM, g_arT L1-resident.
// ============================================================================
__global__ __launch_bounds__(256, 2) void k_attn_mlp(
        const float* __restrict__ um,  const float* __restrict__ Wa2,
        const float* __restrict__ Wm1, const float* __restrict__ bm1,
        const float* __restrict__ Wm2, const float* __restrict__ bm2,
        const float* __restrict__ Wm3, const float* __restrict__ bm3,
        float* __restrict__ out) {
    extern __shared__ __align__(16) float cs[];
    float* sw   = cs;                         // [500][18] = 9000 per chunk
    ull*   ccs  = (ull*)(cs + 9000);          // [16a][16bt] packed (c,c)  512 f
    ull*   w2s  = (ull*)(cs + 9512);          // [16] packed (w*L2E, w*L2E) 32 f
    float* zred = cs + 9544;                  // [8][16] warp Z partials    128 f
    float* invZ = cs + 9672;                  // [16]
    // overlays (barrier-sequenced):
    float* part = cs;                         // [128][64] = 8192
    float* xs   = cs;                         // [16][134] = 2144
    float* h1s  = cs + 2144;                  // [16][66]
    float* h2s  = cs + 3200;                  // [16][34]

    const int t  = threadIdx.x;
    const int b0 = blockIdx.x * 16;
    const bool act = (t < 250);
    const int dp = t & 31, g3 = t >> 5;       // phase-2 mapping

    // constants tables
    if (t < 256) {
        int a = t >> 4, bt = t & 15;
        float c = g_ac[(size_t)(b0 + bt) * NATT + a];
        ccs[t] = pack2(c, c);
    }
    if (t < 16) {
        float w = Wa2[t] * 1.4426950408889634f;
        w2s[t] = pack2(w, w);
    }

    // persistent accumulators
    ull acc[8][2];
    #pragma unroll
    for (int j = 0; j < 8; ++j) { acc[j][0] = 0ull; acc[j][1] = 0ull; }
    float zacc[16];
    #pragma unroll
    for (int bt = 0; bt < 16; ++bt) zacc[bt] = 0.f;

    __syncthreads();

    #pragma unroll 1
    for (int c = 0; c < 2; ++c) {
        // ---- phase 1 (chunk c): thread owns i = 500c + 2t (2 i x 16 bt) ----
        if (act) {
            const int i = 500 * c + 2 * t;
            ull s[16];
            #pragma unroll
            for (int bt = 0; bt < 16; ++bt) s[bt] = 0ull;
            #pragma unroll 4
            for (int a = 0; a < 16; ++a) {
                ull ar = *(const ull*)(g_arT + a * NI + i);   // floats (i, i+1)
                ull w  = w2s[a];
                #pragma unroll
                for (int bt = 0; bt < 16; ++bt)
                    ffma2(s[bt], w, relu_add2(ar, ccs[a * 16 + bt]));
            }
            // exp -> *um -> sw ; Z
            const int il = 2 * t;
            float r0[16], r1[16];
            #pragma unroll
            for (int bt = 0; bt < 16; ++bt) {
                float2 f = unpack2(s[bt]);
                float e0, e1;
                exp2_pair(fminf(f.x, 14.f), fminf(f.y, 14.f), e0, e1);
                zacc[bt] += e0 + e1;
                float2 u = *(const float2*)(um + (size_t)(b0 + bt) * NI + i);
                r0[bt] = e0 * u.x;
                r1[bt] = e1 * u.y;
            }
            #pragma unroll
            for (int bt = 0; bt < 16; bt += 2) {
                *(float2*)(sw + il * 18 + bt)       = make_float2(r0[bt], r0[bt + 1]);
                *(float2*)(sw + (il + 1) * 18 + bt) = make_float2(r1[bt], r1[bt + 1]);
            }
        }
        __syncthreads();

        // ---- phase 2 (chunk c): accumulate user_emb partials ----
        const int ilo = 500 * c, ihi = 500 * (c + 1);
        for (int i = ilo + g3; i < ihi; i += 8) {
            float2 ev = *(const float2*)(g_e_r + (size_t)i * NE + 2 * dp);
            ull ex = pack2(ev.x, ev.x), ey = pack2(ev.y, ev.y);
            const ull* wp = (const ull*)(sw + (i - ilo) * 18);
            #pragma unroll
            for (int j = 0; j < 8; ++j) {
                ull wv = wp[j];
                ffma2(acc[j][0], ex, wv);
                ffma2(acc[j][1], ey, wv);
            }
        }
        __syncthreads();   // sw dead (until next chunk rewrites it)
    }

    // ---- Z reduce: full-warp butterfly, then smem tree ----
    #pragma unroll
    for (int o = 16; o; o >>= 1)
        #pragma unroll
        for (int bt = 0; bt < 16; ++bt)
            zacc[bt] += __shfl_xor_sync(0xffffffffu, zacc[bt], o);
    if ((t & 31) == 0) {
        #pragma unroll
        for (int bt = 0; bt < 16; ++bt) zred[(t >> 5) * 16 + bt] = zacc[bt];
    }
    __syncthreads();
    if (t < 16) {
        float z = 0.f;
        #pragma unroll
        for (int w = 0; w < 8; ++w) z += zred[w * 16 + t];
        invZ[t] = 1.f / z;
    }
    // partials to smem (part overlays sw region; sw is dead)
    #pragma unroll
    for (int j = 0; j < 8; ++j) {
        float2 f0 = unpack2(acc[j][0]);
        float2 f1 = unpack2(acc[j][1]);
        *(float2*)(part + (g3 * 16 + 2 * j    ) * 64 + 2 * dp) = make_float2(f0.x, f1.x);
        *(float2*)(part + (g3 * 16 + 2 * j + 1) * 64 + 2 * dp) = make_float2(f0.y, f1.y);
    }
    __syncthreads();

    // ---- 3a: reduce partials into registers ----
    float uv[4], ev4[4];
    #pragma unroll
    for (int l = 0; l < 4; ++l) {
        int idx = t + 256 * l;
        int btl = idx >> 6, dd = idx & 63;
        float v = 0.f;
        #pragma unroll
        for (int p = 0; p < 8; ++p) v += part[(p * 16 + btl) * 64 + dd];
        uv[l]  = v * invZ[btl];
        ev4[l] = g_e_c[(size_t)(b0 + btl) * NE + dd];
    }
    __syncthreads();   // part dead

    // ---- 3b: write xs ----
    #pragma unroll
    for (int l = 0; l < 4; ++l) {
        int idx = t + 256 * l;
        int btl = idx >> 6, dd = idx & 63;
        xs[btl * 134 + 64 + dd] = uv[l];
        xs[btl * 134 + dd]      = ev4[l];
    }
    __syncthreads();

    // ---- MLP L1: [16,128]@[128,64]; weights from GLOBAL (L1-hot, uniform) ----
    {
        const int row = t & 15, nq = t >> 4;
        ull a4[4];
        #pragma unroll
        for (int j = 0; j < 4; ++j) a4[j] = 0ull;
        #pragma unroll 8
        for (int kk = 0; kk < 64; ++kk) {
            ull a = *(const ull*)(xs + row * 134 + 2 * kk);
            #pragma unroll
            for (int j = 0; j < 4; ++j)
                ffma2(a4[j], a, *(const ull*)(Wm1 + (size_t)(nq + 16 * j) * 128 + 2 * kk));
        }
        #pragma unroll
        for (int j = 0; j < 4; ++j) {
            float2 f = unpack2(a4[j]);
            int n = nq + 16 * j;
            h1s[row * 66 + n] = fmaxf(f.x + f.y + __ldg(bm1 + n), 0.f);
        }
    }
    __syncthreads();

    // ---- MLP L2: [16,64]@[64,32] ----
    {
        const int row = t & 15, nq = t >> 4;
        ull a0 = 0ull, a1 = 0ull;
        #pragma unroll 8
        for (int kk = 0; kk < 32; ++kk) {
            ull h = *(const ull*)(h1s + row * 66 + 2 * kk);
            ffma2(a0, h, *(const ull*)(Wm2 + (size_t)nq * 64 + 2 * kk));
            ffma2(a1, h, *(const ull*)(Wm2 + (size_t)(nq + 16) * 64 + 2 * kk));
        }
        float2 f0 = unpack2(a0), f1 = unpack2(a1);
        h2s[row * 34 + nq]      = fmaxf(f0.x + f0.y + __ldg(bm2 + nq), 0.f);
        h2s[row * 34 + nq + 16] = fmaxf(f1.x + f1.y + __ldg(bm2 + nq + 16), 0.f);
    }
    __syncthreads();

    // ---- MLP L3: dot-32 per row ----
    if (t < 16) {
        ull a = 0ull;
        #pragma unroll
        for (int kk = 0; kk < 16; ++kk)
            ffma2(a, *(const ull*)(h2s + t * 34 + 2 * kk),
                     *(const ull*)(Wm3 + 2 * kk));
        float2 f = unpack2(a);
        out[b0 + t] = f.x + f.y + __ldg(bm3);
    }
}

// ============================================================================
extern "C" void kernel_launch(void* const* d_in, const int* in_sizes, int n_in,
                              void* d_out, int out_size) {
    const float* cand  = (const float*)d_in[0];
    const float* rated = (const float*)d_in[1];
    const float* um    = (const float*)d_in[2];
    const float* We    = (const float*)d_in[3];
    const float* be    = (const float*)d_in[4];
    const float* Wa1   = (const float*)d_in[5];
    const float* ba1   = (const float*)d_in[6];
    const float* Wa2   = (const float*)d_in[7];
    // d_in[8] = ba2: cancels in softmax
    const float* Wm1   = (const float*)d_in[9];
    const float* bm1   = (const float*)d_in[10];
    const float* Wm2   = (const float*)d_in[11];
    const float* bm2   = (const float*)d_in[12];
    const float* Wm3   = (const float*)d_in[13];
    const float* bm3   = (const float*)d_in[14];
    float* out = (float*)d_out;

    const int ESM = 11264 * 4;   // 45056 B
    const int CSM = 9688 * 4;    // 38752 B
    cudaFuncSetAttribute(k_embed,    cudaFuncAttributeMaxDynamicSharedMemorySize, ESM);
    cudaFuncSetAttribute(k_attn_mlp, cudaFuncAttributeMaxDynamicSharedMemorySize, CSM);

    k_embed   <<<144, 512, ESM>>>(cand, rated, We, be, Wa1, ba1);
    k_attn_mlp<<<512, 256, CSM>>>(um, Wa2, Wm1, bm1, Wm2, bm2, Wm3, bm3, out);
}

// round 16
// speedup vs baseline: 1.3128x; 1.0371x over previous
#include <cuda_runtime.h>
#include <cuda_fp16.h>
#include <math.h>

typedef unsigned long long ull;

#define NB   8192
#define NI   1000
#define ND   1000
#define NE   64
#define NATT 16

// ---- scratch (device globals) ----
__device__ __align__(16) float  g_e_c [NB * NE];    // [8192,64]
__device__ __align__(16) float  g_ac  [NB * NATT];  // [8192,16]
__device__ __align__(16) float  g_e_r [NI * NE];    // [1000,64]
__device__ __align__(16) __half g_arT_h[NATT * NI]; // [16,1000] fp16, incl +ba1

// ---- packed f32x2 helpers ----
__device__ __forceinline__ ull pack2(float lo, float hi) {
    ull r; asm("mov.b64 %0, {%1, %2};" : "=l"(r) : "f"(lo), "f"(hi)); return r;
}
__device__ __forceinline__ void ffma2(ull& d, ull a, ull b) {
    asm("fma.rn.f32x2 %0, %1, %2, %0;" : "+l"(d) : "l"(a), "l"(b));
}
__device__ __forceinline__ float2 unpack2(ull v) {
    float2 f; asm("mov.b64 {%0, %1}, %2;" : "=f"(f.x), "=f"(f.y) : "l"(v)); return f;
}
// packed exp2 on f16x2 (one MUFU op, two exps)
__device__ __forceinline__ __half2 ex2h2(__half2 x) {
    unsigned u = *(unsigned*)&x;
    asm("ex2.approx.f16x2 %0, %0;" : "+r"(u));
    return *(__half2*)&u;
}
__device__ __forceinline__ unsigned smem_u32(const void* p) {
    unsigned a;
    asm("{ .reg .u64 t; cvta.to.shared.u64 t, %1; cvt.u32.u64 %0, t; }" : "=r"(a) : "l"(p));
    return a;
}
#define CP_ASYNC16(s, g) asm volatile("cp.async.cg.shared.global [%0], [%1], 16;" :: "r"(s), "l"(g))
#define CP_COMMIT()      asm volatile("cp.async.commit_group;")
#define CP_WAIT(n)       asm volatile("cp.async.wait_group %0;" :: "n"(n))

// ============================================================================
// k_embed: unified embedding GEMM, cp.async double-buffered, 512 threads.
// (unchanged except arT now written as fp16)
// ============================================================================
#define KT    40
#define NTILE 25
#define BUFSZ 5632   // (64+64)*44 floats

__global__ __launch_bounds__(512, 1) void k_embed(
        const float* __restrict__ cand, const float* __restrict__ rated,
        const float* __restrict__ We,   const float* __restrict__ be,
        const float* __restrict__ Wa1,  const float* __restrict__ ba1) {
    extern __shared__ __align__(16) float sm[];   // 2*BUFSZ = 11264 floats

    const int t = threadIdx.x;
    const int b = blockIdx.x;
    const bool isC = (b < 128);
    const int row0   = isC ? b * 64 : (b - 128) * 64;
    const int maxrow = isC ? NB : NI;
    const float* __restrict__ A = isC ? cand : rated;

    const int th = t & 255;
    const int kh = t >> 8;
    const int rq = th >> 4;
    const int nq = th & 15;
    const int kc0 = 20 * kh;

    auto load_tile = [&](int kt, int buf) {
        const int k0 = kt * KT;
        float* base = sm + buf * BUFSZ;
        #pragma unroll
        for (int l = 0; l < 3; ++l) {
            int idx = t + 512 * l;
            if (idx < 640) {
                int r = idx / 10, c = idx - r * 10;
                int gr = row0 + r; if (gr >= maxrow) gr = maxrow - 1;
                CP_ASYNC16(smem_u32(base + r * 44 + 4 * c),
                           A + (size_t)gr * ND + k0 + 4 * c);
            } else if (idx < 1280) {
                int idx2 = idx - 640;
                int r = idx2 / 10, c = idx2 - r * 10;
                CP_ASYNC16(smem_u32(base + 2816 + r * 44 + 4 * c),
                           We + (size_t)r * ND + k0 + 4 * c);
            }
        }
    };

    ull acc[4][4];
    #pragma unroll
    for (int r = 0; r < 4; ++r)
        #pragma unroll
        for (int j = 0; j < 4; ++j) acc[r][j] = 0ull;

    load_tile(0, 0);
    CP_COMMIT();

    for (int kt = 0; kt < NTILE; ++kt) {
        const int cur = kt & 1;
        if (kt < NTILE - 1) {
            load_tile(kt + 1, cur ^ 1);
            CP_COMMIT();
            CP_WAIT(1);
        } else {
            CP_WAIT(0);
        }
        __syncthreads();
        const float* a_sm = sm + cur * BUFSZ + kc0;
        const float* b_sm = sm + cur * BUFSZ + 2816 + kc0;
        #pragma unroll
        for (int c = 0; c < 5; ++c) {
            ull alo[4], ahi[4];
            #pragma unroll
            for (int r = 0; r < 4; ++r) {
                float4 av = *(const float4*)(a_sm + (4 * rq + r) * 44 + 4 * c);
                alo[r] = pack2(av.x, av.y);
                ahi[r] = pack2(av.z, av.w);
            }
            #pragma unroll
            for (int j = 0; j < 4; ++j) {
                float4 bv = *(const float4*)(b_sm + (nq + 16 * j) * 44 + 4 * c);
                ull blo = pack2(bv.x, bv.y), bhi = pack2(bv.z, bv.w);
                #pragma unroll
                for (int r = 0; r < 4; ++r) {
                    ffma2(acc[r][j], alo[r], blo);
                    ffma2(acc[r][j], ahi[r], bhi);
                }
            }
        }
        __syncthreads();
    }

    float* ec = sm;              // [64][66]
    float* w1 = sm + 4224;       // [16][66]
    float* ps = sm + 5280;       // [64][65]

    if (kh) {
        #pragma unroll
        for (int r = 0; r < 4; ++r)
            #pragma unroll
            for (int j = 0; j < 4; ++j) {
                float2 f = unpack2(acc[r][j]);
                ps[(4 * rq + r) * 65 + nq + 16 * j] = f.x + f.y;
            }
    }
    for (int idx = t; idx < 1024; idx += 512) {
        int a = idx >> 6, e = idx & 63;
        w1[a * 66 + e] = Wa1[a * 128 + (isC ? 0 : 64) + e];
    }
    __syncthreads();

    float* eout = isC ? g_e_c : g_e_r;
    if (!kh) {
        #pragma unroll
        for (int r = 0; r < 4; ++r) {
            int row = row0 + 4 * rq + r;
            #pragma unroll
            for (int j = 0; j < 4; ++j) {
                float2 f = unpack2(acc[r][j]);
                int n = nq + 16 * j;
                float v = f.x + f.y + ps[(4 * rq + r) * 65 + n] + __ldg(be + n);
                ec[(4 * rq + r) * 66 + n] = v;
                if (row < maxrow) eout[(size_t)row * NE + n] = v;
            }
        }
    }
    __syncthreads();

    for (int o = t; o < 1024; o += 512) {
        int r = o >> 4, a = o & 15;
        ull s = 0ull;
        #pragma unroll
        for (int e2 = 0; e2 < 32; ++e2)
            ffma2(s, *(const ull*)(ec + r * 66 + 2 * e2),
                     *(const ull*)(w1 + a * 66 + 2 * e2));
        float2 f = unpack2(s);
        int row = row0 + r;
        if (row < maxrow) {
            if (isC) g_ac[(size_t)row * NATT + a] = f.x + f.y;
            else     g_arT_h[a * NI + row] = __float2half_rn(f.x + f.y + __ldg(ba1 + a));
        }
    }
}

// ============================================================================
// k_attn_mlp v5: fp16x2 score pipeline.
// Each thread owns 2 i x all 16 bt. Inner op = hadd2+hmax2+hfma2 (3 instr),
// ex2.approx.f16x2 fed directly (no cvt). Z/user_emb accums stay fp32.
// ============================================================================
__global__ __launch_bounds__(256, 2) void k_attn_mlp(
        const float* __restrict__ um,  const float* __restrict__ Wa2,
        const float* __restrict__ Wm1, const float* __restrict__ bm1,
        const float* __restrict__ Wm2, const float* __restrict__ bm2,
        const float* __restrict__ Wm3, const float* __restrict__ bm3,
        float* __restrict__ out) {
    extern __shared__ __align__(16) float cs[];
    float*   sw   = cs;                       // [500][18] = 9000 per chunk
    __half2* ccs  = (__half2*)(cs + 9000);    // [16a][16bt] (c,c) f16x2 = 256 f
    float*   zred = cs + 9256;                // [8][16]
    float*   invZ = cs + 9384;                // [16]
    // overlays (barrier-sequenced):
    float* part = cs;                         // [128][64] = 8192
    float* xs   = cs;                         // [16][134] = 2144
    float* h1s  = cs + 2144;                  // [16][66]
    float* h2s  = cs + 3200;                  // [16][34]

    const int t  = threadIdx.x;
    const int b0 = blockIdx.x * 16;
    const bool act = (t < 250);
    const int dp = t & 31, g3 = t >> 5;       // phase-2 mapping

    // constants: ccs[a][bt] = (c,c) f16; w2h[a] = (w*L2E, w*L2E) f16 in regs
    if (t < 256) {
        int a = t >> 4, bt = t & 15;
        ccs[t] = __float2half2_rn(g_ac[(size_t)(b0 + bt) * NATT + a]);
    }
    __half2 w2h[16];
    #pragma unroll
    for (int a = 0; a < 16; ++a)
        w2h[a] = __float2half2_rn(__ldg(Wa2 + a) * 1.4426950408889634f);

    // persistent accumulators
    ull acc[8][2];
    #pragma unroll
    for (int j = 0; j < 8; ++j) { acc[j][0] = 0ull; acc[j][1] = 0ull; }
    float zacc[16];
    #pragma unroll
    for (int bt = 0; bt < 16; ++bt) zacc[bt] = 0.f;

    const __half2 hz  = __float2half2_rn(0.f);
    const __half2 h14 = __float2half2_rn(14.f);

    __syncthreads();

    #pragma unroll 1
    for (int c = 0; c < 2; ++c) {
        // ---- phase 1 (chunk c): i = 500c + 2t ; 2 i x 16 bt in f16x2 ----
        if (act) {
            const int i = 500 * c + 2 * t;
            __half2 s2[16];
            #pragma unroll
            for (int bt = 0; bt < 16; ++bt) s2[bt] = hz;
            #pragma unroll 4
            for (int a = 0; a < 16; ++a) {
                __half2 ar2 = *(const __half2*)(g_arT_h + a * NI + i); // (i, i+1)
                __half2 w   = w2h[a];
                const uint2* cp = (const uint2*)(ccs + a * 16);
                #pragma unroll
                for (int q = 0; q < 8; ++q) {
                    uint2 cc = cp[q];
                    __half2 c0 = *(__half2*)&cc.x, c1 = *(__half2*)&cc.y;
                    s2[2*q]   = __hfma2(w, __hmax2(__hadd2(ar2, c0), hz), s2[2*q]);
                    s2[2*q+1] = __hfma2(w, __hmax2(__hadd2(ar2, c1), hz), s2[2*q+1]);
                }
            }
            // exp -> *um -> sw ; Z   (per bt-pair, low transients)
            const int il = 2 * t;
            #pragma unroll
            for (int bt = 0; bt < 16; bt += 2) {
                __half2 e2a = ex2h2(__hmin2(s2[bt],     h14));
                __half2 e2b = ex2h2(__hmin2(s2[bt + 1], h14));
                float e00 = __low2float(e2a), e01 = __high2float(e2a);
                float e10 = __low2float(e2b), e11 = __high2float(e2b);
                zacc[bt]     += e00 + e01;
                zacc[bt + 1] += e10 + e11;
                float2 u0 = *(const float2*)(um + (size_t)(b0 + bt)     * NI + i);
                float2 u1 = *(const float2*)(um + (size_t)(b0 + bt + 1) * NI + i);
                *(float2*)(sw + il * 18 + bt)       = make_float2(e00 * u0.x, e10 * u1.x);
                *(float2*)(sw + (il + 1) * 18 + bt) = make_float2(e01 * u0.y, e11 * u1.y);
            }
        }
        __syncthreads();

        // ---- phase 2 (chunk c): accumulate user_emb partials (fp32) ----
        const int ilo = 500 * c, ihi = 500 * (c + 1);
        for (int i = ilo + g3; i < ihi; i += 8) {
            float2 ev = *(const float2*)(g_e_r + (size_t)i * NE + 2 * dp);
            ull ex = pack2(ev.x, ev.x), ey = pack2(ev.y, ev.y);
            const ull* wp = (const ull*)(sw + (i - ilo) * 18);
            #pragma unroll
            for (int j = 0; j < 8; ++j) {
                ull wv = wp[j];
                ffma2(acc[j][0], ex, wv);
                ffma2(acc[j][1], ey, wv);
            }
        }
        __syncthreads();   // sw dead (until next chunk rewrites it)
    }

    // ---- Z reduce: full-warp butterfly, then smem tree ----
    #pragma unroll
    for (int o = 16; o; o >>= 1)
        #pragma unroll
        for (int bt = 0; bt < 16; ++bt)
            zacc[bt] += __shfl_xor_sync(0xffffffffu, zacc[bt], o);
    if ((t & 31) == 0) {
        #pragma unroll
        for (int bt = 0; bt < 16; ++bt) zred[(t >> 5) * 16 + bt] = zacc[bt];
    }
    __syncthreads();
    if (t < 16) {
        float z = 0.f;
        #pragma unroll
        for (int w = 0; w < 8; ++w) z += zred[w * 16 + t];
        invZ[t] = 1.f / z;
    }
    // partials to smem (part overlays sw region; sw is dead)
    #pragma unroll
    for (int j = 0; j < 8; ++j) {
        float2 f0 = unpack2(acc[j][0]);
        float2 f1 = unpack2(acc[j][1]);
        *(float2*)(part + (g3 * 16 + 2 * j    ) * 64 + 2 * dp) = make_float2(f0.x, f1.x);
        *(float2*)(part + (g3 * 16 + 2 * j + 1) * 64 + 2 * dp) = make_float2(f0.y, f1.y);
    }
    __syncthreads();

    // ---- 3a: reduce partials into registers ----
    float uv[4], ev4[4];
    #pragma unroll
    for (int l = 0; l < 4; ++l) {
        int idx = t + 256 * l;
        int btl = idx >> 6, dd = idx & 63;
        float v = 0.f;
        #pragma unroll
        for (int p = 0; p < 8; ++p) v += part[(p * 16 + btl) * 64 + dd];
        uv[l]  = v * invZ[btl];
        ev4[l] = g_e_c[(size_t)(b0 + btl) * NE + dd];
    }
    __syncthreads();   // part dead

    // ---- 3b: write xs ----
    #pragma unroll
    for (int l = 0; l < 4; ++l) {
        int idx = t + 256 * l;
        int btl = idx >> 6, dd = idx & 63;
        xs[btl * 134 + 64 + dd] = uv[l];
        xs[btl * 134 + dd]      = ev4[l];
    }
    __syncthreads();

    // ---- MLP L1: [16,128]@[128,64]; weights from GLOBAL (L1-hot, uniform) ----
    {
        const int row = t & 15, nq = t >> 4;
        ull a4[4];
        #pragma unroll
        for (int j = 0; j < 4; ++j) a4[j] = 0ull;
        #pragma unroll 8
        for (int kk = 0; kk < 64; ++kk) {
            ull a = *(const ull*)(xs + row * 134 + 2 * kk);
            #pragma unroll
            for (int j = 0; j < 4; ++j)
                ffma2(a4[j], a, *(const ull*)(Wm1 + (size_t)(nq + 16 * j) * 128 + 2 * kk));
        }
        #pragma unroll
        for (int j = 0; j < 4; ++j) {
            float2 f = unpack2(a4[j]);
            int n = nq + 16 * j;
            h1s[row * 66 + n] = fmaxf(f.x + f.y + __ldg(bm1 + n), 0.f);
        }
    }
    __syncthreads();

    // ---- MLP L2: [16,64]@[64,32] ----
    {
        const int row = t & 15, nq = t >> 4;
        ull a0 = 0ull, a1 = 0ull;
        #pragma unroll 8
        for (int kk = 0; kk < 32; ++kk) {
            ull h = *(const ull*)(h1s + row * 66 + 2 * kk);
            ffma2(a0, h, *(const ull*)(Wm2 + (size_t)nq * 64 + 2 * kk));
            ffma2(a1, h, *(const ull*)(Wm2 + (size_t)(nq + 16) * 64 + 2 * kk));
        }
        float2 f0 = unpack2(a0), f1 = unpack2(a1);
        h2s[row * 34 + nq]      = fmaxf(f0.x + f0.y + __ldg(bm2 + nq), 0.f);
        h2s[row * 34 + nq + 16] = fmaxf(f1.x + f1.y + __ldg(bm2 + nq + 16), 0.f);
    }
    __syncthreads();

    // ---- MLP L3: dot-32 per row ----
    if (t < 16) {
        ull a = 0ull;
        #pragma unroll
        for (int kk = 0; kk < 16; ++kk)
            ffma2(a, *(const ull*)(h2s + t * 34 + 2 * kk),
                     *(const ull*)(Wm3 + 2 * kk));
        float2 f = unpack2(a);
        out[b0 + t] = f.x + f.y + __ldg(bm3);
    }
}

// ============================================================================
extern "C" void kernel_launch(void* const* d_in, const int* in_sizes, int n_in,
                              void* d_out, int out_size) {
    const float* cand  = (const float*)d_in[0];
    const float* rated = (const float*)d_in[1];
    const float* um    = (const float*)d_in[2];
    const float* We    = (const float*)d_in[3];
    const float* be    = (const float*)d_in[4];
    const float* Wa1   = (const float*)d_in[5];
    const float* ba1   = (const float*)d_in[6];
    const float* Wa2   = (const float*)d_in[7];
    // d_in[8] = ba2: cancels in softmax
    const float* Wm1   = (const float*)d_in[9];
    const float* bm1   = (const float*)d_in[10];
    const float* Wm2   = (const float*)d_in[11];
    const float* bm2   = (const float*)d_in[12];
    const float* Wm3   = (const float*)d_in[13];
    const float* bm3   = (const float*)d_in[14];
    float* out = (float*)d_out;

    const int ESM = 11264 * 4;   // 45056 B
    const int CSM = 9400 * 4;    // 37600 B
    cudaFuncSetAttribute(k_embed,    cudaFuncAttributeMaxDynamicSharedMemorySize, ESM);
    cudaFuncSetAttribute(k_attn_mlp, cudaFuncAttributeMaxDynamicSharedMemorySize, CSM);

    k_embed   <<<144, 512, ESM>>>(cand, rated, We, be, Wa1, ba1);
    k_attn_mlp<<<512, 256, CSM>>>(um, Wa2, Wm1, bm1, Wm2, bm2, Wm3, bm3, out);
}